// round 13
// baseline (speedup 1.0000x reference)
#include <cuda_runtime.h>

// out[(b*8+h)*Np1^2 + r*Np1 + c] =
//   token[h]                                   if r==0 || c==0
//   emb[ st[(b*N + (r-1))*N + (c-1)] ][h]      otherwise
//
// Grid = (Np1, B); block = N threads. Thread tid handles column c = tid+1 of
// row (b, r) and writes all H=8 planes. The 8-float emb row is fetched with
// two LDS.128 — gather cost paid ONCE per (b,r,c) instead of per head.
// emb staged in smem at a pitch of 9 float4s so the LDS.128 chunk index is
// (stv*9 + {0,1}) mod 8 ≡ (stv + {0,1}) mod 8 — uniform over all 8 quad-bank
// groups for random stv (the 32B-pitch layout hits only 4). Zero div/mod.

__global__ void __launch_bounds__(512)
wbe_plane8(const int* __restrict__ st,
           const float* __restrict__ emb,
           const float* __restrict__ token,
           float* __restrict__ out,
           int B, int N, int embRows)
{
    extern __shared__ float sh[];            // embRows*36 floats, then 8 token floats
    float* s_tok = sh + embRows * 36;        // 36*4 B pitch => 16B-aligned tail

    const int tid = threadIdx.x;
    const int nsh = embRows * 8;
    for (int i = tid; i < nsh; i += blockDim.x) {
        int s = i >> 3, h = i & 7;
        sh[s * 36 + h] = emb[i];             // row s at float4 slot s*9
    }
    if (tid < 8) s_tok[tid] = token[tid];
    __syncthreads();

    const int r   = blockIdx.x;              // 0..N
    const int b   = blockIdx.y;              // 0..B-1
    const int Np1 = N + 1;
    const int plane = Np1 * Np1;
    const int obase = (b * 8) * plane + r * Np1;

    float vals[8];
    if (r == 0) {
        #pragma unroll
        for (int h = 0; h < 8; ++h) vals[h] = s_tok[h];
    } else {
        const int stv = __ldg(&st[(b * N + (r - 1)) * N + tid]);  // c-1 = tid
        const float4* e4 = reinterpret_cast<const float4*>(sh) + stv * 9;
        float4 v0 = e4[0];
        float4 v1 = e4[1];
        vals[0] = v0.x; vals[1] = v0.y; vals[2] = v0.z; vals[3] = v0.w;
        vals[4] = v1.x; vals[5] = v1.y; vals[6] = v1.z; vals[7] = v1.w;
    }

    float* p = out + obase + tid + 1;        // c = tid+1
    #pragma unroll
    for (int h = 0; h < 8; ++h) {
        *p = vals[h];
        p += plane;
    }

    if (tid == 0) {                          // c == 0 column: graph token
        float* q = out + obase;
        #pragma unroll
        for (int h = 0; h < 8; ++h) {
            *q = s_tok[h];
            q += plane;
        }
    }
}

// Generic fallback (safety net for unexpected shapes)
__global__ void wbe_kernel_generic(const int* __restrict__ st,
                                   const float* __restrict__ emb,
                                   const float* __restrict__ token,
                                   float* __restrict__ out,
                                   int B, int N, int H, int embRows,
                                   long long total)
{
    extern __shared__ float sh[];
    float* s_emb = sh;
    float* s_tok = sh + (size_t)embRows * H;
    const int nsh = embRows * H;
    for (int i = threadIdx.x; i < nsh; i += blockDim.x) s_emb[i] = emb[i];
    for (int i = threadIdx.x; i < H; i += blockDim.x) s_tok[i] = token[i];
    __syncthreads();

    long long idx = (long long)blockIdx.x * blockDim.x + threadIdx.x;
    if (idx >= total) return;

    const int Np1 = N + 1;
    int c = (int)(idx % Np1);
    long long t = idx / Np1;
    int r = (int)(t % Np1);
    int bb = (int)(t / Np1);

    const float* src;
    if (r == 0 || c == 0) {
        src = s_tok;
    } else {
        int stv = st[((long long)bb * N + (r - 1)) * N + (c - 1)];
        src = s_emb + (size_t)stv * H;
    }
    const long long plane = (long long)Np1 * Np1;
    long long o = ((long long)bb * H) * plane + (long long)r * Np1 + c;
    for (int hh = 0; hh < H; ++hh)
        out[o + (long long)hh * plane] = src[hh];
}

extern "C" void kernel_launch(void* const* d_in, const int* in_sizes, int n_in,
                              void* d_out, int out_size)
{
    // inputs (metadata order):
    // 0: spatial_types [E] int32, 1: graph_index [2,E] int32, 2: batch [B*N] int32,
    // 3: num_graphs, 4: max_nodes, 5: emb_weight [(S+1),H] f32, 6: graph_token [1,H,1] f32
    const int*   st    = (const int*)  d_in[0];
    const float* emb   = (const float*)d_in[5];
    const float* token = (const float*)d_in[6];
    float* out = (float*)d_out;

    const long long E = in_sizes[0];
    const int num_nodes = in_sizes[2];
    const int H = in_sizes[6];
    const int embRows = in_sizes[5] / H;
    const int N = (int)(E / num_nodes);   // E = B*N*N, num_nodes = B*N
    const int B = num_nodes / N;
    const int Np1 = N + 1;

    if (H == 8 && N >= 64 && N <= 1024 && embRows <= 1024 &&
        (long long)B * H * Np1 * Np1 < (1LL << 31)) {
        dim3 grid(Np1, B);
        const size_t smem = (size_t)(embRows * 36 + 8) * sizeof(float);
        wbe_plane8<<<grid, N, smem>>>(st, emb, token, out, B, N, embRows);
    } else {
        const long long total = (long long)B * Np1 * Np1;
        const int threads = 256;
        const long long blocks = (total + threads - 1) / threads;
        const size_t smem = ((size_t)embRows * H + H) * sizeof(float);
        wbe_kernel_generic<<<(unsigned)blocks, threads, smem>>>(
            st, emb, token, out, B, N, H, embRows, total);
    }
}